// round 15
// baseline (speedup 1.0000x reference)
#include <cuda_runtime.h>
#include <cuda_bf16.h>
#include <cstdint>

// ---------------- problem constants ----------------
#define N_TOT 8192
#define D     128
#define IPC_C 512
#define ROW0  7680            // bz - IPC
#define NCOL  7680            // unmasked columns [0, 7680)
#define BM    128
#define BN    256
#define NTIL  (NCOL / BN)     // 30 column tiles
#define ETIL  (1024 / BN)     // tiles [0,4) = easy region (exact boundary)
#define NBLK  (NTIL * (IPC_C / BM))   // 120 blocks = one wave
#define LDB   136             // bf16 smem row stride; 68 uint32

// ---------------- device globals ----------------
__device__ float g_invr[IPC_C];           // inverse norms of the 512 A-rows
__device__ float g_part[NTIL * IPC_C];    // [colTile][row] partial (col-scaled) maxima
__device__ int   g_done;                  // zero-init; reset each replay

// smem: A bf16[128][136] + B bf16[256][136] + snorm float[384]
#define OFF_SNORM (BM * LDB * 2 + BN * LDB * 2)
#define SMEM_BYTES (OFF_SNORM + 384 * 4)

__global__ void __launch_bounds__(512, 1) hse_kernel(const float* __restrict__ fvec,
                                                     const float* __restrict__ a_scl,
                                                     float* __restrict__ out) {
    extern __shared__ char smraw[];
    __nv_bfloat16* As = (__nv_bfloat16*)smraw;
    __nv_bfloat16* Bs = As + BM * LDB;
    float* snorm = (float*)(smraw + OFF_SNORM);   // [0,128)=A rows, [128,384)=B rows

    const int tid  = threadIdx.x;
    const int lane = tid & 31;
    const int w    = tid >> 5;
    const int wm   = w >> 2;        // 0..3 -> 32-row strip
    const int wn   = w & 3;         // 0..3 -> 64-col strip
    const int q    = lane >> 2;     // 0..7
    const int tig  = lane & 3;      // 0..3
    const int bid  = blockIdx.x;
    const int rowBase = ROW0 + (bid / NTIL) * BM;
    const int colBase = (bid % NTIL) * BN;

    if (tid < 384) snorm[tid] = 0.f;
    __syncthreads();

    // ---- stage A raw->bf16; norm partials via 3 shfls + pipelined smem REDS ----
    #pragma unroll
    for (int t = 0; t < 8; t++) {
        int r = w + t * 16;                  // warp-uniform row
        float4 v = __ldg((const float4*)(fvec + (size_t)(rowBase + r) * D) + lane);
        float ss = v.x * v.x + v.y * v.y + v.z * v.z + v.w * v.w;
        ss += __shfl_xor_sync(0xffffffffu, ss, 1);
        ss += __shfl_xor_sync(0xffffffffu, ss, 2);
        ss += __shfl_xor_sync(0xffffffffu, ss, 4);
        if ((lane & 7) == 0) atomicAdd(&snorm[r], ss);   // fire-and-forget REDS
        __nv_bfloat162 p0 = __floats2bfloat162_rn(v.x, v.y);
        __nv_bfloat162 p1 = __floats2bfloat162_rn(v.z, v.w);
        *(uint2*)(As + r * LDB + lane * 4) = make_uint2(*(uint32_t*)&p0, *(uint32_t*)&p1);
    }
    // ---- stage B raw->bf16 likewise ----
    #pragma unroll
    for (int t = 0; t < 16; t++) {
        int r = w + t * 16;
        float4 v = __ldg((const float4*)(fvec + (size_t)(colBase + r) * D) + lane);
        float ss = v.x * v.x + v.y * v.y + v.z * v.z + v.w * v.w;
        ss += __shfl_xor_sync(0xffffffffu, ss, 1);
        ss += __shfl_xor_sync(0xffffffffu, ss, 2);
        ss += __shfl_xor_sync(0xffffffffu, ss, 4);
        if ((lane & 7) == 0) atomicAdd(&snorm[128 + r], ss);
        __nv_bfloat162 p0 = __floats2bfloat162_rn(v.x, v.y);
        __nv_bfloat162 p1 = __floats2bfloat162_rn(v.z, v.w);
        *(uint2*)(Bs + r * LDB + lane * 4) = make_uint2(*(uint32_t*)&p0, *(uint32_t*)&p1);
    }
    __syncthreads();

    // ---- norms -> inverse norms (A rows to global, B rows in place) ----
    if (tid < 384) {
        float s = snorm[tid];
        float inv = rsqrtf(s);
        if (!(s > 1e-24f)) inv = 1e12f;
        if (tid < 128) g_invr[(bid / NTIL) * BM + tid] = inv;  // dup writes benign
        else           snorm[tid] = inv;
    }
    __syncthreads();
    const float* invB = snorm + 128;

    // ---- mainloop: 8 K-steps of m16n8k16 bf16 (proven R8 core) ----
    float acc[2][8][4];
    #pragma unroll
    for (int mt = 0; mt < 2; mt++)
        #pragma unroll
        for (int nt = 0; nt < 8; nt++)
            #pragma unroll
            for (int e = 0; e < 4; e++) acc[mt][nt][e] = 0.f;

    const uint32_t* A32 = (const uint32_t*)As;   // row*68 + kpair
    const uint32_t* B32 = (const uint32_t*)Bs;
    const int rA0 = wm * 32 + q;
    const int rB0 = wn * 64 + q;

    #pragma unroll
    for (int s = 0; s < 8; s++) {
        const int ko = s * 8 + tig;
        uint32_t af[2][4];
        #pragma unroll
        for (int mt = 0; mt < 2; mt++) {
            int b0 = (rA0 + mt * 16) * 68 + ko;
            af[mt][0] = A32[b0];
            af[mt][1] = A32[b0 + 8 * 68];
            af[mt][2] = A32[b0 + 4];
            af[mt][3] = A32[b0 + 8 * 68 + 4];
        }
        uint32_t bf[8][2];
        #pragma unroll
        for (int nt = 0; nt < 8; nt++) {
            int b0 = (rB0 + nt * 8) * 68 + ko;
            bf[nt][0] = B32[b0];
            bf[nt][1] = B32[b0 + 4];
        }
        #pragma unroll
        for (int mt = 0; mt < 2; mt++)
            #pragma unroll
            for (int nt = 0; nt < 8; nt++)
                asm volatile(
                    "mma.sync.aligned.m16n8k16.row.col.f32.bf16.bf16.f32 "
                    "{%0,%1,%2,%3}, {%4,%5,%6,%7}, {%8,%9}, {%0,%1,%2,%3};"
                    : "+f"(acc[mt][nt][0]), "+f"(acc[mt][nt][1]),
                      "+f"(acc[mt][nt][2]), "+f"(acc[mt][nt][3])
                    : "r"(af[mt][0]), "r"(af[mt][1]), "r"(af[mt][2]), "r"(af[mt][3]),
                      "r"(bf[nt][0]), "r"(bf[nt][1]));
    }
    __syncthreads();   // all As/Bs reads done before pm overwrites As

    // ---- epilogue: scale by column inv-norm, then row max ----
    float* pm = (float*)smraw;    // [4(wn)][128]  (overlaps As only; snorm untouched)
    #pragma unroll
    for (int mt = 0; mt < 2; mt++) {
        float mlo = -1e30f, mhi = -1e30f;
        #pragma unroll
        for (int nt = 0; nt < 8; nt++) {
            float2 ic = *(const float2*)(invB + wn * 64 + nt * 8 + tig * 2);
            mlo = fmaxf(mlo, fmaxf(acc[mt][nt][0] * ic.x, acc[mt][nt][1] * ic.y));
            mhi = fmaxf(mhi, fmaxf(acc[mt][nt][2] * ic.x, acc[mt][nt][3] * ic.y));
        }
        #pragma unroll
        for (int o = 1; o < 4; o <<= 1) {
            mlo = fmaxf(mlo, __shfl_xor_sync(0xffffffffu, mlo, o));
            mhi = fmaxf(mhi, __shfl_xor_sync(0xffffffffu, mhi, o));
        }
        if (tig == 0) {
            int r = wm * 32 + mt * 16 + q;
            pm[wn * 128 + r]     = mlo;
            pm[wn * 128 + r + 8] = mhi;
        }
    }
    __syncthreads();

    if (tid < BM) {
        float m = fmaxf(fmaxf(pm[tid], pm[128 + tid]),
                        fmaxf(pm[256 + tid], pm[384 + tid]));
        g_part[(bid % NTIL) * IPC_C + (bid / NTIL) * BM + tid] = m;
    }
    __syncthreads();

    // ---- last-block-done fused finalize ----
    __shared__ int isLast;
    __shared__ float sred;
    if (tid == 0) {
        __threadfence();
        isLast = (atomicAdd(&g_done, 1) == NBLK - 1);
    }
    __syncthreads();
    if (!isLast) return;

    if (tid == 0) { __threadfence(); sred = 0.f; }
    __syncthreads();

    float e = -1e30f, h = -1e30f;
    #pragma unroll
    for (int j = 0; j < ETIL; j++)     e = fmaxf(e, g_part[j * IPC_C + tid]);
    #pragma unroll
    for (int j = ETIL; j < NTIL; j++)  h = fmaxf(h, g_part[j * IPC_C + tid]);
    float loss = log1pf(expf((h - e) * 10.0f * g_invr[tid]));   // 1/SIGMA1 = 10
    #pragma unroll
    for (int o = 16; o; o >>= 1) loss += __shfl_xor_sync(0xffffffffu, loss, o);
    if (lane == 0) atomicAdd(&sred, loss);
    __syncthreads();

    if (tid == 0) {
        out[0] = a_scl[0] * sred * (1.0f / 512.0f);
        g_done = 0;      // reset for the next graph replay
    }
}

extern "C" void kernel_launch(void* const* d_in, const int* in_sizes, int n_in,
                              void* d_out, int out_size) {
    const float* fvec = (const float*)d_in[0];   // [8192,128] f32
    // d_in[1] = Lvec (dead in the reference math)
    const float* a    = (const float*)d_in[2];   // scalar f32
    float* out = (float*)d_out;

    cudaFuncSetAttribute(hse_kernel,
                         cudaFuncAttributeMaxDynamicSharedMemorySize, SMEM_BYTES);

    hse_kernel<<<NBLK, 512, SMEM_BYTES>>>(fvec, a, out);
}

// round 16
// speedup vs baseline: 1.4442x; 1.4442x over previous
#include <cuda_runtime.h>
#include <cuda_bf16.h>
#include <cstdint>

// ---------------- problem constants ----------------
#define N_TOT 8192
#define D     128
#define IPC_C 512
#define ROW0  7680            // bz - IPC
#define NCOL  7680            // unmasked columns [0, 7680)
#define BM    128
#define BN    256
#define NTIL  (NCOL / BN)     // 30 column tiles
#define ETIL  (1024 / BN)     // tiles [0,4) = easy region (exact boundary)
#define NBLK  (NTIL * (IPC_C / BM))   // 120 blocks = one wave
#define LDB   136             // bf16 smem row stride (bf16 units); 68 uint32

// ---------------- device globals ----------------
__device__ __nv_bfloat16 g_bf[N_TOT * D];   // normalized bf16
__device__ float g_part[NTIL * IPC_C];      // [colTile][row] partial maxima
__device__ int   g_done;                    // zero-init; reset each replay

#define CP_ASYNC16(dst_u32, src_ptr) \
    asm volatile("cp.async.cg.shared.global [%0], [%1], 16;" \
                 :: "r"(dst_u32), "l"(src_ptr) : "memory")
#define CP_COMMIT()  asm volatile("cp.async.commit_group;" ::: "memory")
#define CP_WAIT0()   asm volatile("cp.async.wait_group 0;" ::: "memory")

// ---------------- kernel 1: normalize -> bf16; 2 rows per warp (ILP) ----------------
__global__ void __launch_bounds__(256) prep_kernel(const float* __restrict__ f) {
    const int lane = threadIdx.x & 31;
    const int w    = threadIdx.x >> 5;
    const int r0   = blockIdx.x * 16 + w * 2;     // warp handles rows r0, r0+1

    float4 v0 = ((const float4*)(f + (size_t)r0 * D))[lane];
    float4 v1 = ((const float4*)(f + (size_t)(r0 + 1) * D))[lane];
    float s0 = v0.x * v0.x + v0.y * v0.y + v0.z * v0.z + v0.w * v0.w;
    float s1 = v1.x * v1.x + v1.y * v1.y + v1.z * v1.z + v1.w * v1.w;
    #pragma unroll
    for (int o = 16; o; o >>= 1) {                // two independent chains interleave
        s0 += __shfl_xor_sync(0xffffffffu, s0, o);
        s1 += __shfl_xor_sync(0xffffffffu, s1, o);
    }
    float i0 = rsqrtf(s0); if (!(s0 > 1e-24f)) i0 = 1e12f;
    float i1 = rsqrtf(s1); if (!(s1 > 1e-24f)) i1 = 1e12f;

    __nv_bfloat162 a0 = __floats2bfloat162_rn(v0.x * i0, v0.y * i0);
    __nv_bfloat162 a1 = __floats2bfloat162_rn(v0.z * i0, v0.w * i0);
    __nv_bfloat162 b0 = __floats2bfloat162_rn(v1.x * i1, v1.y * i1);
    __nv_bfloat162 b1 = __floats2bfloat162_rn(v1.z * i1, v1.w * i1);
    *(uint2*)(g_bf + (size_t)r0 * D + lane * 4) =
        make_uint2(*(uint32_t*)&a0, *(uint32_t*)&a1);
    *(uint2*)(g_bf + (size_t)(r0 + 1) * D + lane * 4) =
        make_uint2(*(uint32_t*)&b0, *(uint32_t*)&b1);
}

// ---------------- kernel 2: bf16 m16n8k16 GEMM + row-max + fused finalize ----------------
// (byte-identical to the proven R8 core)
// 512 threads = 16 warps (4m x 4n); warp tile 32x64.
// smem: A bf16[128][136] + B bf16[256][136] = 104448 B
#define SMEM_BYTES (BM * LDB * 2 + BN * LDB * 2)

__global__ void __launch_bounds__(512, 1) gemm_kernel(const float* __restrict__ a_scl,
                                                      float* __restrict__ out) {
    extern __shared__ char smraw[];
    __nv_bfloat16* As = (__nv_bfloat16*)smraw;
    __nv_bfloat16* Bs = As + BM * LDB;

    const int tid  = threadIdx.x;
    const int lane = tid & 31;
    const int w    = tid >> 5;
    const int wm   = w >> 2;        // 0..3 -> 32-row strip
    const int wn   = w & 3;         // 0..3 -> 64-col strip
    const int q    = lane >> 2;     // 0..7
    const int tig  = lane & 3;      // 0..3
    const int rowBase = ROW0 + blockIdx.y * BM;
    const int colBase = blockIdx.x * BN;

    const uint32_t sA = (uint32_t)__cvta_generic_to_shared(As);
    const uint32_t sB = (uint32_t)__cvta_generic_to_shared(Bs);

    // ---- stage A (128 rows) and B (256 rows), 16 x 16B chunks per row ----
    #pragma unroll
    for (int t = 0; t < 4; t++) {
        int idx = tid + t * 512;
        int r = idx >> 4, c = idx & 15;
        CP_ASYNC16(sA + r * (LDB * 2) + c * 16,
                   g_bf + (size_t)(rowBase + r) * D + c * 8);
    }
    #pragma unroll
    for (int t = 0; t < 8; t++) {
        int idx = tid + t * 512;
        int r = idx >> 4, c = idx & 15;
        CP_ASYNC16(sB + r * (LDB * 2) + c * 16,
                   g_bf + (size_t)(colBase + r) * D + c * 8);
    }
    CP_COMMIT();
    CP_WAIT0();
    __syncthreads();

    float acc[2][8][4];
    #pragma unroll
    for (int mt = 0; mt < 2; mt++)
        #pragma unroll
        for (int nt = 0; nt < 8; nt++)
            #pragma unroll
            for (int e = 0; e < 4; e++) acc[mt][nt][e] = 0.f;

    const uint32_t* A32 = (const uint32_t*)As;   // row*68 + kpair
    const uint32_t* B32 = (const uint32_t*)Bs;
    const int rA0 = wm * 32 + q;
    const int rB0 = wn * 64 + q;

    #pragma unroll
    for (int s = 0; s < 8; s++) {            // 8 K-steps of k16
        const int ko = s * 8 + tig;
        uint32_t af[2][4];
        #pragma unroll
        for (int mt = 0; mt < 2; mt++) {
            int b0 = (rA0 + mt * 16) * 68 + ko;
            af[mt][0] = A32[b0];
            af[mt][1] = A32[b0 + 8 * 68];
            af[mt][2] = A32[b0 + 4];
            af[mt][3] = A32[b0 + 8 * 68 + 4];
        }
        uint32_t bf[8][2];
        #pragma unroll
        for (int nt = 0; nt < 8; nt++) {
            int b0 = (rB0 + nt * 8) * 68 + ko;
            bf[nt][0] = B32[b0];
            bf[nt][1] = B32[b0 + 4];
        }
        #pragma unroll
        for (int mt = 0; mt < 2; mt++)
            #pragma unroll
            for (int nt = 0; nt < 8; nt++)
                asm volatile(
                    "mma.sync.aligned.m16n8k16.row.col.f32.bf16.bf16.f32 "
                    "{%0,%1,%2,%3}, {%4,%5,%6,%7}, {%8,%9}, {%0,%1,%2,%3};"
                    : "+f"(acc[mt][nt][0]), "+f"(acc[mt][nt][1]),
                      "+f"(acc[mt][nt][2]), "+f"(acc[mt][nt][3])
                    : "r"(af[mt][0]), "r"(af[mt][1]), "r"(af[mt][2]), "r"(af[mt][3]),
                      "r"(bf[nt][0]), "r"(bf[nt][1]));
    }
    __syncthreads();   // all smem reads done before reuse

    // ---- row max: thread -> quad shfl -> cross-warp via smem ----
    float* pm = (float*)smraw;    // [4(wn)][128]
    #pragma unroll
    for (int mt = 0; mt < 2; mt++) {
        float mlo = -2.f, mhi = -2.f;
        #pragma unroll
        for (int nt = 0; nt < 8; nt++) {
            mlo = fmaxf(mlo, fmaxf(acc[mt][nt][0], acc[mt][nt][1]));
            mhi = fmaxf(mhi, fmaxf(acc[mt][nt][2], acc[mt][nt][3]));
        }
        #pragma unroll
        for (int o = 1; o < 4; o <<= 1) {
            mlo = fmaxf(mlo, __shfl_xor_sync(0xffffffffu, mlo, o));
            mhi = fmaxf(mhi, __shfl_xor_sync(0xffffffffu, mhi, o));
        }
        if (tig == 0) {
            int r = wm * 32 + mt * 16 + q;
            pm[wn * 128 + r]     = mlo;
            pm[wn * 128 + r + 8] = mhi;
        }
    }
    __syncthreads();

    if (tid < BM) {
        float m = fmaxf(fmaxf(pm[tid], pm[128 + tid]),
                        fmaxf(pm[256 + tid], pm[384 + tid]));
        g_part[blockIdx.x * IPC_C + blockIdx.y * BM + tid] = m;
    }
    __syncthreads();

    // ---- last-block-done fused finalize ----
    __shared__ int isLast;
    __shared__ float red[512];
    if (tid == 0) {
        __threadfence();
        isLast = (atomicAdd(&g_done, 1) == NBLK - 1);
    }
    __syncthreads();
    if (!isLast) return;
    if (tid == 0) __threadfence();
    __syncthreads();

    float e = -2.f, h = -2.f;
    #pragma unroll
    for (int j = 0; j < ETIL; j++)     e = fmaxf(e, g_part[j * IPC_C + tid]);
    #pragma unroll
    for (int j = ETIL; j < NTIL; j++)  h = fmaxf(h, g_part[j * IPC_C + tid]);
    red[tid] = log1pf(expf((h - e) * 10.0f));   // 1/SIGMA1 = 10
    __syncthreads();
    #pragma unroll
    for (int s2 = 256; s2; s2 >>= 1) {
        if (tid < s2) red[tid] += red[tid + s2];
        __syncthreads();
    }
    if (tid == 0) {
        out[0] = a_scl[0] * red[0] * (1.0f / 512.0f);
        g_done = 0;      // reset for the next graph replay
    }
}

extern "C" void kernel_launch(void* const* d_in, const int* in_sizes, int n_in,
                              void* d_out, int out_size) {
    const float* fvec = (const float*)d_in[0];   // [8192,128] f32
    // d_in[1] = Lvec (dead in the reference math)
    const float* a    = (const float*)d_in[2];   // scalar f32
    float* out = (float*)d_out;

    cudaFuncSetAttribute(gemm_kernel,
                         cudaFuncAttributeMaxDynamicSharedMemorySize, SMEM_BYTES);

    prep_kernel<<<N_TOT / 16, 256>>>(fvec);
    gemm_kernel<<<dim3(NTIL, IPC_C / BM), 512, SMEM_BYTES>>>(a, out);
}